// round 2
// baseline (speedup 1.0000x reference)
#include <cuda_runtime.h>

// x: (8, 48, 48, 48, 64) fp32.  K = reshape(x, (B, C, N)), C=64, N=110592.
// Row c of K is the contiguous chunk x[b, c*N : (c+1)*N].
#define CCH   64
#define NCOL  110592
#define BATCH 8
#define CN    (CCH * NCOL)

#define CHUNK2 512
#define NCH2   (NCOL / CHUNK2)       // 216 partial-Gram chunks
#define GTK    16
#define TN     128                   // n-tile for the weights kernel

typedef unsigned long long ull;

// Static device scratch (no runtime allocation allowed).
__device__ float g_part[BATCH * NCH2 * CCH * CCH];   // 28.3 MB partial Grams
__device__ float g_aff [BATCH * CCH * CCH];          // sigmoid(G@G)

// ---- packed f32x2 helpers (FFMA2 — PTX-only on sm_103a) --------------------
__device__ __forceinline__ void fma2(ull& acc, ull a, ull b) {
    asm("fma.rn.f32x2 %0, %1, %2, %0;" : "+l"(acc) : "l"(a), "l"(b));
}
__device__ __forceinline__ ull pack2(float a) {
    ull d; asm("mov.b64 %0, {%1, %1};" : "=l"(d) : "f"(a)); return d;
}

// ---------------------------------------------------------------------------
// Kernel 1: partial Gram. 128 threads = two independent 64-thread halves.
// Each half computes the full 64x64 Gram of its own 512-column chunk with an
// 8x8 register tile per thread (f32x2), writing its own g_part slice.
// grid (NCH2/2, BATCH).
// ---------------------------------------------------------------------------
__global__ void __launch_bounds__(128, 4) gram_partial(const float* __restrict__ x) {
    __shared__ float Ks[2][GTK][CCH + 4];   // 8.7 KB; row stride 68*4=272B (16B-aligned)

    const int tid = threadIdx.x;
    const int h   = tid >> 6;               // half 0/1
    const int ht  = tid & 63;
    const int ty  = ht >> 3;                // rows ty*8 .. ty*8+7
    const int tx  = ht & 7;                 // cols tx*8 .. tx*8+7
    const int b   = blockIdx.y;
    const long n0 = ((long)blockIdx.x * 2 + h) * CHUNK2;
    const float* gptr = x + (long)b * CN + (long)ht * NCOL + n0;  // row ht of this chunk

    ull acc[8][4] = {};                     // 8 rows x 4 col-pairs (= 8x8 floats)

    // prefetch stage 0: 64 rows x 16 cols per half; thread loads row ht, 4 float4
    float4 pf[4];
#pragma unroll
    for (int j = 0; j < 4; j++) pf[j] = *(const float4*)(gptr + j * 4);

    for (int k0 = 0; k0 < CHUNK2; k0 += GTK) {
        // store prefetched tile (transposed: Ks[kk][c])
#pragma unroll
        for (int j = 0; j < 4; j++) {
            Ks[h][j * 4 + 0][ht] = pf[j].x;
            Ks[h][j * 4 + 1][ht] = pf[j].y;
            Ks[h][j * 4 + 2][ht] = pf[j].z;
            Ks[h][j * 4 + 3][ht] = pf[j].w;
        }
        __syncthreads();

        // prefetch next stage while computing this one
        if (k0 + GTK < CHUNK2) {
#pragma unroll
            for (int j = 0; j < 4; j++)
                pf[j] = *(const float4*)(gptr + k0 + GTK + j * 4);
        }

#pragma unroll
        for (int kk = 0; kk < GTK; kk++) {
            float4 a0 = *(const float4*)&Ks[h][kk][ty * 8];
            float4 a1 = *(const float4*)&Ks[h][kk][ty * 8 + 4];
            ulonglong2 q0 = *(const ulonglong2*)&Ks[h][kk][tx * 8];
            ulonglong2 q1 = *(const ulonglong2*)&Ks[h][kk][tx * 8 + 4];
            ull bp[4] = {q0.x, q0.y, q1.x, q1.y};
            float ar[8] = {a0.x, a0.y, a0.z, a0.w, a1.x, a1.y, a1.z, a1.w};
#pragma unroll
            for (int i = 0; i < 8; i++) {
                ull ap = pack2(ar[i]);
#pragma unroll
                for (int jp = 0; jp < 4; jp++) fma2(acc[i][jp], ap, bp[jp]);
            }
        }
        __syncthreads();
    }

    // write partial Gram (bit patterns of packed pairs == two floats)
    float* outp = g_part + ((long)b * NCH2 + blockIdx.x * 2 + h) * (CCH * CCH);
#pragma unroll
    for (int i = 0; i < 8; i++) {
        float* row = outp + (ty * 8 + i) * CCH + tx * 8;
        *(ulonglong2*)(row)     = make_ulonglong2(acc[i][0], acc[i][1]);
        *(ulonglong2*)(row + 4) = make_ulonglong2(acc[i][2], acc[i][3]);
    }
}

// ---------------------------------------------------------------------------
// Kernel 2: reduce partials -> G, m3 = G@G (G symmetric), sigmoid. grid(BATCH).
// ---------------------------------------------------------------------------
__global__ void m3_sigmoid() {
    __shared__ float Gs[CCH * CCH];

    const int b   = blockIdx.x;
    const int tid = threadIdx.x;            // 256

    // deterministic reduction over 216 partials, float4-vectorized
    const float4* base = (const float4*)(g_part + (long)b * NCH2 * (CCH * CCH));
    for (int i4 = tid; i4 < (CCH * CCH) / 4; i4 += 256) {
        float4 s = make_float4(0.f, 0.f, 0.f, 0.f);
#pragma unroll 8
        for (int ch = 0; ch < NCH2; ch++) {
            float4 v = base[(long)ch * (CCH * CCH / 4) + i4];
            s.x += v.x; s.y += v.y; s.z += v.z; s.w += v.w;
        }
        *(float4*)&Gs[i4 * 4] = s;
    }
    __syncthreads();

    // m3[c][e] = sum_d G[c][d]*G[e][d]  (symmetric G), then sigmoid
    const int c  = tid >> 2;
    const int e0 = (tid & 3) * 16;
    for (int e = e0; e < e0 + 16; e++) {
        float s = 0.0f;
#pragma unroll
        for (int d = 0; d < CCH; d++)
            s = fmaf(Gs[c * CCH + d], Gs[e * CCH + d], s);
        g_aff[b * (CCH * CCH) + c * CCH + e] = 1.0f / (1.0f + __expf(-s));
    }
}

// ---------------------------------------------------------------------------
// Kernel 3: out = x + gamma * (A @ K). 64 x 128 tile, 128 threads, 8x8/thread.
// grid (NCOL/TN, BATCH). x[c,n] == Ks[c][n], so epilogue reads the SMEM tile.
// ---------------------------------------------------------------------------
__global__ void __launch_bounds__(128, 4) weights_out(const float* __restrict__ x,
                                                      const float* __restrict__ gamma_p,
                                                      float* __restrict__ out) {
    __shared__ float As[CCH * CCH];         // 16 KB (affinity, symmetric)
    __shared__ float Ks[CCH][TN];           // 32 KB

    const int tid = threadIdx.x;            // 128
    const int b   = blockIdx.y;
    const long n0 = (long)blockIdx.x * TN;
    const float* Kb = x + (long)b * CN;

    // load affinity (1024 float4 / 128 threads)
    {
        const float4* src = (const float4*)(g_aff + b * (CCH * CCH));
        for (int i = tid; i < (CCH * CCH) / 4; i += 128)
            ((float4*)As)[i] = src[i];
    }
    // load K tile: 64 rows x 128 cols; thread (r = tid>>1, half = tid&1) loads 64B*?
    {
        const int r  = tid >> 1;
        const int hf = tid & 1;
        const float* src = Kb + (long)r * NCOL + n0 + hf * 64;
#pragma unroll
        for (int i = 0; i < 16; i++)
            *(float4*)&Ks[r][hf * 64 + i * 4] = *(const float4*)(src + i * 4);
    }
    __syncthreads();

    const int ty = tid >> 4;                // c rows ty*8 .. +7
    const int tx = tid & 15;                // n cols tx*8 .. +7

    ull acc[8][4] = {};

#pragma unroll 4
    for (int d = 0; d < CCH; d++) {
        // A[c][d] == A[d][c] (symmetric) -> read row d contiguously
        float4 a0 = *(const float4*)&As[d * CCH + ty * 8];
        float4 a1 = *(const float4*)&As[d * CCH + ty * 8 + 4];
        ulonglong2 q0 = *(const ulonglong2*)&Ks[d][tx * 8];
        ulonglong2 q1 = *(const ulonglong2*)&Ks[d][tx * 8 + 4];
        ull bp[4] = {q0.x, q0.y, q1.x, q1.y};
        float ar[8] = {a0.x, a0.y, a0.z, a0.w, a1.x, a1.y, a1.z, a1.w};
#pragma unroll
        for (int i = 0; i < 8; i++) {
            ull ap = pack2(ar[i]);
#pragma unroll
            for (int jp = 0; jp < 4; jp++) fma2(acc[i][jp], ap, bp[jp]);
        }
    }

    const ull gp = pack2(*gamma_p);

#pragma unroll
    for (int i = 0; i < 8; i++) {
        const int c = ty * 8 + i;
        ulonglong2 k0 = *(const ulonglong2*)&Ks[c][tx * 8];
        ulonglong2 k1 = *(const ulonglong2*)&Ks[c][tx * 8 + 4];
        ull r0 = k0.x, r1 = k0.y, r2 = k1.x, r3 = k1.y;
        fma2(r0, gp, acc[i][0]);            // r = gamma*acc + x
        fma2(r1, gp, acc[i][1]);
        fma2(r2, gp, acc[i][2]);
        fma2(r3, gp, acc[i][3]);
        float* dst = out + (long)b * CN + (long)c * NCOL + n0 + tx * 8;
        *(ulonglong2*)(dst)     = make_ulonglong2(r0, r1);
        *(ulonglong2*)(dst + 4) = make_ulonglong2(r2, r3);
    }
}

// ---------------------------------------------------------------------------
extern "C" void kernel_launch(void* const* d_in, const int* in_sizes, int n_in,
                              void* d_out, int out_size) {
    const float* x     = (const float*)d_in[0];
    const float* gamma = (const float*)d_in[1];
    float*       out   = (float*)d_out;

    gram_partial<<<dim3(NCH2 / 2, BATCH), 128>>>(x);
    m3_sigmoid  <<<BATCH, 256>>>();
    weights_out <<<dim3(NCOL / TN, BATCH), 128>>>(x, gamma, out);
}

// round 5
// speedup vs baseline: 2.1250x; 2.1250x over previous
#include <cuda_runtime.h>
#include <cuda_bf16.h>
#include <stdint.h>

// x: (8, 48, 48, 48, 64) fp32.  K = reshape(x, (B, C, N)), C=64, N=110592.
#define CCH    64
#define NCOL   110592
#define BATCH  8
#define CN     (CCH * NCOL)

#define GCHUNK 2048
#define NCHUNK (NCOL / GCHUNK)        // 54 partial-Gram chunks
#define GKS    32                     // k-step per iteration
#define GITERS (GCHUNK / GKS)         // 64

#define WTN    96                     // n-tile for weights kernel
#define WBLK   (NCOL / WTN)           // 1152

// ---------------- static device scratch ------------------------------------
__device__ float         g_part[BATCH * NCHUNK * CCH * CCH];  // 7.1 MB
__device__ __nv_bfloat16 g_aff_bf[BATCH * CCH * CCH];

// ---------------- helpers ---------------------------------------------------
// pack two f32 -> bf16x2 (lo at low half)
__device__ __forceinline__ uint32_t pk2(float lo, float hi) {
    uint32_t r;
    asm("cvt.rn.bf16x2.f32 %0, %1, %2;" : "=r"(r) : "f"(hi), "f"(lo));
    return r;
}
// m16n8k16 bf16 HMMA (base PTX feature, works on plain sm_103 target)
__device__ __forceinline__ void mma16816(float* c, const uint32_t* a, const uint32_t* b) {
    asm volatile(
        "mma.sync.aligned.m16n8k16.row.col.f32.bf16.bf16.f32 "
        "{%0,%1,%2,%3}, {%4,%5,%6,%7}, {%8,%9}, {%0,%1,%2,%3};"
        : "+f"(c[0]), "+f"(c[1]), "+f"(c[2]), "+f"(c[3])
        : "r"(a[0]), "r"(a[1]), "r"(a[2]), "r"(a[3]), "r"(b[0]), "r"(b[1]));
}

// ---------------------------------------------------------------------------
// Kernel 1: partial Gram via HMMA.  Block = 64 channels x 2048-col chunk.
// Both mma operands read the same K-major bf16 tile Ts[c][k]:
//   A-frag reg = Ts[m_row][2k..2k+1]   (one LDS.32)
//   B-frag reg = Ts[n_col][2k..2k+1]   (one LDS.32)
// Row stride 40 bf16 (20 banks) -> all fragment loads conflict-free.
// grid (NCHUNK, BATCH), 128 threads (4 warps); warp w owns m-rows 16w..16w+15.
// ---------------------------------------------------------------------------
#define TSTR 40

__global__ void __launch_bounds__(128) gram_tc(const float* __restrict__ x) {
    __shared__ __nv_bfloat16 Ts[64 * TSTR];   // 5 KB

    const int tid  = threadIdx.x;
    const int w    = tid >> 5;
    const int lane = tid & 31;
    const int gid  = lane >> 2;               // 0..7
    const int tig  = lane & 3;                // 0..3
    const int b    = blockIdx.y;
    const long n0  = (long)blockIdx.x * GCHUNK;

    const int lr = tid >> 1, lh = tid & 1;    // loader: row, col-half
    const float* src = x + (long)b * CN + (long)lr * NCOL + n0 + lh * 16;

    float4 pf[4];
#pragma unroll
    for (int j = 0; j < 4; j++) pf[j] = *(const float4*)(src + j * 4);

    float acc[8][4] = {};                     // 8 n-tiles x 4 f32

    for (int it = 0; it < GITERS; it++) {
        __syncthreads();                      // previous compute done reading Ts
        // convert + store this thread's 16 floats (row lr, cols lh*16..+15)
        {
            uint4 s0 = make_uint4(pk2(pf[0].x, pf[0].y), pk2(pf[0].z, pf[0].w),
                                  pk2(pf[1].x, pf[1].y), pk2(pf[1].z, pf[1].w));
            uint4 s1 = make_uint4(pk2(pf[2].x, pf[2].y), pk2(pf[2].z, pf[2].w),
                                  pk2(pf[3].x, pf[3].y), pk2(pf[3].z, pf[3].w));
            __nv_bfloat16* d = &Ts[lr * TSTR + lh * 16];
            *(uint4*)(d)     = s0;
            *(uint4*)(d + 8) = s1;
        }
        // prefetch next k-step while this one computes
        if (it + 1 < GITERS) {
            const float* s = src + (it + 1) * GKS;
#pragma unroll
            for (int j = 0; j < 4; j++) pf[j] = *(const float4*)(s + j * 4);
        }
        __syncthreads();

#pragma unroll
        for (int kk = 0; kk < 2; kk++) {      // two k16 sub-steps
            const int kc = kk * 16 + tig * 2;
            uint32_t a[4];
            a[0] = *(const uint32_t*)&Ts[(w * 16 + gid) * TSTR + kc];
            a[1] = *(const uint32_t*)&Ts[(w * 16 + gid + 8) * TSTR + kc];
            a[2] = *(const uint32_t*)&Ts[(w * 16 + gid) * TSTR + kc + 8];
            a[3] = *(const uint32_t*)&Ts[(w * 16 + gid + 8) * TSTR + kc + 8];
#pragma unroll
            for (int nt = 0; nt < 8; nt++) {
                uint32_t bb[2];
                bb[0] = *(const uint32_t*)&Ts[(nt * 8 + gid) * TSTR + kc];
                bb[1] = *(const uint32_t*)&Ts[(nt * 8 + gid) * TSTR + kc + 8];
                mma16816(acc[nt], a, bb);
            }
        }
    }

    // write partial Gram: C[c][c2]; c-frag: rows gid / gid+8, cols 2tig..+1
    float* op = g_part + ((long)b * NCHUNK + blockIdx.x) * (CCH * CCH);
#pragma unroll
    for (int nt = 0; nt < 8; nt++) {
        const int c0  = w * 16 + gid;
        const int col = nt * 8 + tig * 2;
        *(float2*)&op[c0 * CCH + col]       = make_float2(acc[nt][0], acc[nt][1]);
        *(float2*)&op[(c0 + 8) * CCH + col] = make_float2(acc[nt][2], acc[nt][3]);
    }
}

// ---------------------------------------------------------------------------
// Kernel 2: reduce partials -> G, m3 = G@G (symmetric), sigmoid -> bf16.
// ---------------------------------------------------------------------------
__global__ void m3_sigmoid() {
    __shared__ float Gs[CCH * CCH];
    const int b   = blockIdx.x;
    const int tid = threadIdx.x;              // 256

    const float4* base = (const float4*)(g_part + (long)b * NCHUNK * (CCH * CCH));
    for (int i4 = tid; i4 < (CCH * CCH) / 4; i4 += 256) {
        float4 s = make_float4(0.f, 0.f, 0.f, 0.f);
        for (int ch = 0; ch < NCHUNK; ch++) {
            float4 v = base[(long)ch * (CCH * CCH / 4) + i4];
            s.x += v.x; s.y += v.y; s.z += v.z; s.w += v.w;
        }
        *(float4*)&Gs[i4 * 4] = s;
    }
    __syncthreads();

    const int c  = tid >> 2;
    const int e0 = (tid & 3) * 16;
    for (int e = e0; e < e0 + 16; e++) {
        float s = 0.0f;
#pragma unroll
        for (int d = 0; d < CCH; d++)
            s = fmaf(Gs[c * CCH + d], Gs[e * CCH + d], s);
        g_aff_bf[b * (CCH * CCH) + c * CCH + e] =
            __float2bfloat16(1.0f / (1.0f + __expf(-s)));
    }
}

// ---------------------------------------------------------------------------
// Kernel 3: out = x + gamma * (A @ K) via HMMA.  M = 64 channels, N = 96 cols,
// K = 64.  A-op = bf16 affinity (row-major, stride 72 -> conflict-free frags);
// B-op = x^T tile, built by bank-clean SMEM transpose (Xs stride 100 floats).
// grid (WBLK, BATCH), 128 threads; warp w owns n-cols 24w..24w+23.
// ---------------------------------------------------------------------------
#define XSTR 100
#define ASTR 72
#define BSTR 72

__global__ void __launch_bounds__(128) weights_tc(const float* __restrict__ x,
                                                  const float* __restrict__ gamma_p,
                                                  float* __restrict__ out) {
    __shared__ float         Xs[64 * XSTR];   // 25600 B
    __shared__ __nv_bfloat16 As[64 * ASTR];   //  9216 B
    __shared__ __nv_bfloat16 Bs[WTN * BSTR];  // 13824 B  (total 48640 < 48 KB)

    const int tid  = threadIdx.x;
    const int w    = tid >> 5;
    const int lane = tid & 31;
    const int gid  = lane >> 2;
    const int tig  = lane & 3;
    const int b    = blockIdx.y;
    const long n0  = (long)blockIdx.x * WTN;

    // load x tile fp32 -> Xs[64][96] (padded rows), coalesced
    {
        const int r = tid >> 1, h = tid & 1;
        const float* s = x + (long)b * CN + (long)r * NCOL + n0 + h * 48;
#pragma unroll
        for (int i = 0; i < 12; i++)
            *(float4*)&Xs[r * XSTR + h * 48 + i * 4] = *(const float4*)(s + i * 4);
    }
    // load affinity bf16 -> As[64][64] (stride 72)
    {
        const int r = tid >> 1, h = tid & 1;
        const uint4* s = (const uint4*)(g_aff_bf + b * (CCH * CCH) + r * CCH + h * 32);
#pragma unroll
        for (int i = 0; i < 4; i++)
            *(uint4*)&As[r * ASTR + h * 32 + i * 8] = s[i];
    }
    __syncthreads();

    // build Bs[n][d] = bf16(Xs[d][n]) — column reads are conflict-free
    if (tid < WTN) {
        const int n = tid;
#pragma unroll
        for (int j = 0; j < 8; j++) {
            uint32_t p[4];
#pragma unroll
            for (int q = 0; q < 4; q++) {
                float f0 = Xs[(j * 8 + q * 2) * XSTR + n];
                float f1 = Xs[(j * 8 + q * 2 + 1) * XSTR + n];
                p[q] = pk2(f0, f1);
            }
            *(uint4*)&Bs[n * BSTR + j * 8] = make_uint4(p[0], p[1], p[2], p[3]);
        }
    }
    __syncthreads();

    float acc[4][3][4] = {};                  // m-tile x n-tile x frag

#pragma unroll
    for (int kt = 0; kt < 4; kt++) {
        const int kc = kt * 16 + tig * 2;
        uint32_t a[4][4];
#pragma unroll
        for (int mt = 0; mt < 4; mt++) {
            a[mt][0] = *(const uint32_t*)&As[(mt * 16 + gid) * ASTR + kc];
            a[mt][1] = *(const uint32_t*)&As[(mt * 16 + gid + 8) * ASTR + kc];
            a[mt][2] = *(const uint32_t*)&As[(mt * 16 + gid) * ASTR + kc + 8];
            a[mt][3] = *(const uint32_t*)&As[(mt * 16 + gid + 8) * ASTR + kc + 8];
        }
#pragma unroll
        for (int nt = 0; nt < 3; nt++) {
            uint32_t bb[2];
            bb[0] = *(const uint32_t*)&Bs[(w * 24 + nt * 8 + gid) * BSTR + kc];
            bb[1] = *(const uint32_t*)&Bs[(w * 24 + nt * 8 + gid) * BSTR + kc + 8];
#pragma unroll
            for (int mt = 0; mt < 4; mt++) mma16816(acc[mt][nt], a[mt], bb);
        }
    }

    const float g = *gamma_p;
#pragma unroll
    for (int mt = 0; mt < 4; mt++) {
#pragma unroll
        for (int nt = 0; nt < 3; nt++) {
            const int c0 = mt * 16 + gid;
            const int n  = w * 24 + nt * 8 + tig * 2;
            float2 x0 = *(float2*)&Xs[c0 * XSTR + n];
            float2 x1 = *(float2*)&Xs[(c0 + 8) * XSTR + n];
            float* d0 = out + (long)b * CN + (long)c0 * NCOL + n0 + n;
            float* d1 = d0 + 8l * NCOL;
            d0[0] = fmaf(g, acc[mt][nt][0], x0.x);
            d0[1] = fmaf(g, acc[mt][nt][1], x0.y);
            d1[0] = fmaf(g, acc[mt][nt][2], x1.x);
            d1[1] = fmaf(g, acc[mt][nt][3], x1.y);
        }
    }
}

// ---------------------------------------------------------------------------
extern "C" void kernel_launch(void* const* d_in, const int* in_sizes, int n_in,
                              void* d_out, int out_size) {
    const float* x     = (const float*)d_in[0];
    const float* gamma = (const float*)d_in[1];
    float*       out   = (float*)d_out;

    gram_tc    <<<dim3(NCHUNK, BATCH), 128>>>(x);
    m3_sigmoid <<<BATCH, 256>>>();
    weights_tc <<<dim3(WBLK, BATCH), 128>>>(x, gamma, out);
}

// round 7
// speedup vs baseline: 2.1577x; 1.0154x over previous
#include <cuda_runtime.h>
#include <cuda_bf16.h>
#include <stdint.h>

// x: (8, 48, 48, 48, 64) fp32.  K = reshape(x, (B, C, N)), C=64, N=110592.
#define CCH    64
#define NCOL   110592
#define BATCH  8
#define CN     (CCH * NCOL)

#define GCHUNK 1024
#define NCHUNK (NCOL / GCHUNK)        // 108 partial-Gram chunks
#define GKS    32
#define GITERS (GCHUNK / GKS)         // 32

#define WTN    96
#define WBLK   (NCOL / WTN)           // 1152

// ---------------- static device scratch ------------------------------------
__device__ float         g_part[BATCH * NCHUNK * CCH * CCH];  // 14.2 MB
__device__ float         g_G[BATCH * CCH * CCH];
__device__ __nv_bfloat16 g_aff_bf[BATCH * CCH * CCH];

// ---------------- helpers ---------------------------------------------------
__device__ __forceinline__ uint32_t pk2(float lo, float hi) {
    uint32_t r;
    asm("cvt.rn.bf16x2.f32 %0, %1, %2;" : "=r"(r) : "f"(hi), "f"(lo));
    return r;
}
__device__ __forceinline__ void mma16816(float* c, const uint32_t* a, const uint32_t* b) {
    asm volatile(
        "mma.sync.aligned.m16n8k16.row.col.f32.bf16.bf16.f32 "
        "{%0,%1,%2,%3}, {%4,%5,%6,%7}, {%8,%9}, {%0,%1,%2,%3};"
        : "+f"(c[0]), "+f"(c[1]), "+f"(c[2]), "+f"(c[3])
        : "r"(a[0]), "r"(a[1]), "r"(a[2]), "r"(a[3]), "r"(b[0]), "r"(b[1]));
}

// ---------------------------------------------------------------------------
// Kernel 1: partial Gram via HMMA.  Block = 64 channels x 1024-col chunk.
// grid (NCHUNK, BATCH), 128 threads.  Ts stride 40 -> conflict-free frags.
// ---------------------------------------------------------------------------
#define TSTR 40

__global__ void __launch_bounds__(128) gram_tc(const float* __restrict__ x) {
    __shared__ __nv_bfloat16 Ts[64 * TSTR];

    const int tid  = threadIdx.x;
    const int w    = tid >> 5;
    const int lane = tid & 31;
    const int gid  = lane >> 2;
    const int tig  = lane & 3;
    const int b    = blockIdx.y;
    const long n0  = (long)blockIdx.x * GCHUNK;

    const int lr = tid >> 1, lh = tid & 1;
    const float* src = x + (long)b * CN + (long)lr * NCOL + n0 + lh * 16;

    float4 pf[4];
#pragma unroll
    for (int j = 0; j < 4; j++) pf[j] = *(const float4*)(src + j * 4);

    float acc[8][4] = {};

    for (int it = 0; it < GITERS; it++) {
        __syncthreads();
        {
            uint4 s0 = make_uint4(pk2(pf[0].x, pf[0].y), pk2(pf[0].z, pf[0].w),
                                  pk2(pf[1].x, pf[1].y), pk2(pf[1].z, pf[1].w));
            uint4 s1 = make_uint4(pk2(pf[2].x, pf[2].y), pk2(pf[2].z, pf[2].w),
                                  pk2(pf[3].x, pf[3].y), pk2(pf[3].z, pf[3].w));
            __nv_bfloat16* d = &Ts[lr * TSTR + lh * 16];
            *(uint4*)(d)     = s0;
            *(uint4*)(d + 8) = s1;
        }
        if (it + 1 < GITERS) {
            const float* s = src + (it + 1) * GKS;
#pragma unroll
            for (int j = 0; j < 4; j++) pf[j] = *(const float4*)(s + j * 4);
        }
        __syncthreads();

#pragma unroll
        for (int kk = 0; kk < 2; kk++) {
            const int kc = kk * 16 + tig * 2;
            uint32_t a[4];
            a[0] = *(const uint32_t*)&Ts[(w * 16 + gid) * TSTR + kc];
            a[1] = *(const uint32_t*)&Ts[(w * 16 + gid + 8) * TSTR + kc];
            a[2] = *(const uint32_t*)&Ts[(w * 16 + gid) * TSTR + kc + 8];
            a[3] = *(const uint32_t*)&Ts[(w * 16 + gid + 8) * TSTR + kc + 8];
#pragma unroll
            for (int nt = 0; nt < 8; nt++) {
                uint32_t bb[2];
                bb[0] = *(const uint32_t*)&Ts[(nt * 8 + gid) * TSTR + kc];
                bb[1] = *(const uint32_t*)&Ts[(nt * 8 + gid) * TSTR + kc + 8];
                mma16816(acc[nt], a, bb);
            }
        }
    }

    float* op = g_part + ((long)b * NCHUNK + blockIdx.x) * (CCH * CCH);
#pragma unroll
    for (int nt = 0; nt < 8; nt++) {
        const int c0  = w * 16 + gid;
        const int col = nt * 8 + tig * 2;
        *(float2*)&op[c0 * CCH + col]       = make_float2(acc[nt][0], acc[nt][1]);
        *(float2*)&op[(c0 + 8) * CCH + col] = make_float2(acc[nt][2], acc[nt][3]);
    }
}

// ---------------------------------------------------------------------------
// Kernel 2a: reduce partials -> G.  grid (16, BATCH), 256 threads.
// ---------------------------------------------------------------------------
__global__ void reduce_g() {
    const int b    = blockIdx.y;
    const int elem = blockIdx.x * 256 + threadIdx.x;
    const float* p = g_part + (long)b * NCHUNK * (CCH * CCH) + elem;

    float s0 = 0.f, s1 = 0.f, s2 = 0.f, s3 = 0.f;
#pragma unroll 1
    for (int ch = 0; ch < NCHUNK; ch += 4) {
        s0 += p[(long)(ch + 0) * (CCH * CCH)];
        s1 += p[(long)(ch + 1) * (CCH * CCH)];
        s2 += p[(long)(ch + 2) * (CCH * CCH)];
        s3 += p[(long)(ch + 3) * (CCH * CCH)];
    }
    g_G[b * (CCH * CCH) + elem] = (s0 + s1) + (s2 + s3);
}

// ---------------------------------------------------------------------------
// Kernel 2b: m3 = G@G (symmetric), sigmoid -> bf16.  grid (BATCH).
// ---------------------------------------------------------------------------
__global__ void m3_sigmoid() {
    __shared__ float Gs[CCH * CCH];
    const int b   = blockIdx.x;
    const int tid = threadIdx.x;              // 256

    const float4* src = (const float4*)(g_G + b * (CCH * CCH));
    for (int i = tid; i < (CCH * CCH) / 4; i += 256)
        ((float4*)Gs)[i] = src[i];
    __syncthreads();

    const int c  = tid >> 2;
    const int e0 = (tid & 3) * 16;
    for (int e = e0; e < e0 + 16; e++) {
        float s = 0.0f;
#pragma unroll
        for (int d = 0; d < CCH; d++)
            s = fmaf(Gs[c * CCH + d], Gs[e * CCH + d], s);
        g_aff_bf[b * (CCH * CCH) + c * CCH + e] =
            __float2bfloat16(1.0f / (1.0f + __expf(-s)));
    }
}

// ---------------------------------------------------------------------------
// Kernel 3: out = x + gamma * (A @ K) via HMMA.  M=64, N=96, K=64.
// 256 threads / 8 warps: wm = w>>2 -> m-rows wm*32..+31; wn = w&3 -> n-cols
// wn*24..+23.  grid (WBLK, BATCH).
// ---------------------------------------------------------------------------
#define XSTR 100
#define ASTR 72
#define BSTR 72

__global__ void __launch_bounds__(256) weights_tc(const float* __restrict__ x,
                                                  const float* __restrict__ gamma_p,
                                                  float* __restrict__ out) {
    __shared__ float         Xs[64 * XSTR];   // 25600 B
    __shared__ __nv_bfloat16 As[64 * ASTR];   //  9216 B
    __shared__ __nv_bfloat16 Bs[WTN * BSTR];  // 13824 B  (total 48640 <= 48K)

    const int tid  = threadIdx.x;
    const int w    = tid >> 5;
    const int lane = tid & 31;
    const int gid  = lane >> 2;
    const int tig  = lane & 3;
    const int wm   = w >> 2;
    const int wn   = w & 3;
    const int b    = blockIdx.y;
    const long n0  = (long)blockIdx.x * WTN;

    // load x tile fp32 -> Xs[64][96] (4 threads/row, 24 floats each)
    {
        const int r = tid >> 2, q = tid & 3;
        const float* s = x + (long)b * CN + (long)r * NCOL + n0 + q * 24;
        float* d = &Xs[r * XSTR + q * 24];
#pragma unroll
        for (int i = 0; i < 6; i++)
            *(float4*)(d + i * 4) = *(const float4*)(s + i * 4);
    }
    // load affinity bf16 -> As[64][64] (stride 72); 4 threads/row, 16 bf16 each
    {
        const int r = tid >> 2, h = tid & 3;
        const uint4* s = (const uint4*)(g_aff_bf + b * (CCH * CCH) + r * CCH + h * 16);
        *(uint4*)&As[r * ASTR + h * 16]     = s[0];
        *(uint4*)&As[r * ASTR + h * 16 + 8] = s[1];
    }
    __syncthreads();

    // build Bs[n][d] = bf16(Xs[d][n]); 2 threads per column
    if (tid < 192) {
        const int n  = tid >> 1;
        const int d0 = (tid & 1) * 32;
#pragma unroll
        for (int j = 0; j < 4; j++) {
            uint32_t p[4];
#pragma unroll
            for (int q = 0; q < 4; q++) {
                float f0 = Xs[(d0 + j * 8 + q * 2) * XSTR + n];
                float f1 = Xs[(d0 + j * 8 + q * 2 + 1) * XSTR + n];
                p[q] = pk2(f0, f1);
            }
            *(uint4*)&Bs[n * BSTR + d0 + j * 8] = make_uint4(p[0], p[1], p[2], p[3]);
        }
    }
    __syncthreads();

    float acc[2][3][4] = {};

#pragma unroll
    for (int kt = 0; kt < 4; kt++) {
        const int kc = kt * 16 + tig * 2;
        uint32_t a[2][4];
#pragma unroll
        for (int mi = 0; mi < 2; mi++) {
            const int mr = (wm * 2 + mi) * 16;
            a[mi][0] = *(const uint32_t*)&As[(mr + gid) * ASTR + kc];
            a[mi][1] = *(const uint32_t*)&As[(mr + gid + 8) * ASTR + kc];
            a[mi][2] = *(const uint32_t*)&As[(mr + gid) * ASTR + kc + 8];
            a[mi][3] = *(const uint32_t*)&As[(mr + gid + 8) * ASTR + kc + 8];
        }
#pragma unroll
        for (int nt = 0; nt < 3; nt++) {
            uint32_t bb[2];
            bb[0] = *(const uint32_t*)&Bs[(wn * 24 + nt * 8 + gid) * BSTR + kc];
            bb[1] = *(const uint32_t*)&Bs[(wn * 24 + nt * 8 + gid) * BSTR + kc + 8];
#pragma unroll
            for (int mi = 0; mi < 2; mi++) mma16816(acc[mi][nt], a[mi], bb);
        }
    }

    const float g = *gamma_p;
#pragma unroll
    for (int mi = 0; mi < 2; mi++) {
#pragma unroll
        for (int nt = 0; nt < 3; nt++) {
            const int c0 = (wm * 2 + mi) * 16 + gid;
            const int n  = wn * 24 + nt * 8 + tig * 2;
            float2 x0 = *(float2*)&Xs[c0 * XSTR + n];
            float2 x1 = *(float2*)&Xs[(c0 + 8) * XSTR + n];
            float* d0 = out + (long)b * CN + (long)c0 * NCOL + n0 + n;
            float* d1 = d0 + 8l * NCOL;
            d0[0] = fmaf(g, acc[mi][nt][0], x0.x);
            d0[1] = fmaf(g, acc[mi][nt][1], x0.y);
            d1[0] = fmaf(g, acc[mi][nt][2], x1.x);
            d1[1] = fmaf(g, acc[mi][nt][3], x1.y);
        }
    }
}

// ---------------------------------------------------------------------------
extern "C" void kernel_launch(void* const* d_in, const int* in_sizes, int n_in,
                              void* d_out, int out_size) {
    const float* x     = (const float*)d_in[0];
    const float* gamma = (const float*)d_in[1];
    float*       out   = (float*)d_out;

    gram_tc    <<<dim3(NCHUNK, BATCH), 128>>>(x);
    reduce_g   <<<dim3(16, BATCH), 256>>>();
    m3_sigmoid <<<BATCH, 256>>>();
    weights_tc <<<dim3(WBLK, BATCH), 256>>>(x, gamma, out);
}

// round 12
// speedup vs baseline: 2.6737x; 1.2391x over previous
#include <cuda_runtime.h>
#include <cuda_bf16.h>
#include <stdint.h>

// x: (8, 48, 48, 48, 64) fp32.  K = reshape(x, (B, C, N)), C=64, N=110592.
#define CCH    64
#define NCOL   110592
#define BATCH  8
#define CN     (CCH * NCOL)

#define GCHUNK 1024
#define NCHUNK (NCOL / GCHUNK)        // 108 partial-Gram chunks
#define GKS    32
#define GITERS (GCHUNK / GKS)         // 32

#define WTN    96
#define WBLK   (NCOL / WTN)           // 1152

// ---------------- static device scratch ------------------------------------
__device__ float         g_part[BATCH * NCHUNK * CCH * CCH];  // 14.2 MB
__device__ float         g_G[BATCH * CCH * CCH];
__device__ __nv_bfloat16 g_aff_bf[BATCH * CCH * CCH];

// ---------------- helpers ---------------------------------------------------
__device__ __forceinline__ uint32_t pk2(float lo, float hi) {
    uint32_t r;
    asm("cvt.rn.bf16x2.f32 %0, %1, %2;" : "=r"(r) : "f"(hi), "f"(lo));
    return r;
}
__device__ __forceinline__ void mma16816(float* c, const uint32_t* a, const uint32_t* b) {
    asm volatile(
        "mma.sync.aligned.m16n8k16.row.col.f32.bf16.bf16.f32 "
        "{%0,%1,%2,%3}, {%4,%5,%6,%7}, {%8,%9}, {%0,%1,%2,%3};"
        : "+f"(c[0]), "+f"(c[1]), "+f"(c[2]), "+f"(c[3])
        : "r"(a[0]), "r"(a[1]), "r"(a[2]), "r"(a[3]), "r"(b[0]), "r"(b[1]));
}
__device__ __forceinline__ void ldsm4(uint32_t* r, uint32_t a) {
    asm volatile("ldmatrix.sync.aligned.m8n8.x4.shared.b16 {%0,%1,%2,%3}, [%4];"
                 : "=r"(r[0]), "=r"(r[1]), "=r"(r[2]), "=r"(r[3]) : "r"(a));
}
__device__ __forceinline__ void ldsm4t(uint32_t* r, uint32_t a) {
    asm volatile("ldmatrix.sync.aligned.m8n8.x4.trans.shared.b16 {%0,%1,%2,%3}, [%4];"
                 : "=r"(r[0]), "=r"(r[1]), "=r"(r[2]), "=r"(r[3]) : "r"(a));
}
__device__ __forceinline__ void ldsm2t(uint32_t* r, uint32_t a) {
    asm volatile("ldmatrix.sync.aligned.m8n8.x2.trans.shared.b16 {%0,%1}, [%2];"
                 : "=r"(r[0]), "=r"(r[1]) : "r"(a));
}
__device__ __forceinline__ uint32_t smem_u32(const void* p) {
    return (uint32_t)__cvta_generic_to_shared(p);
}

// ---------------------------------------------------------------------------
// Kernel 1: partial Gram via HMMA + ldmatrix.  Block = 64 ch x 1024-col chunk.
// grid (NCHUNK, BATCH), 128 threads.  Ts stride 40 bf16 -> conflict-free LDSM.
// ---------------------------------------------------------------------------
#define TSTR 40

__global__ void __launch_bounds__(128) gram_tc(const float* __restrict__ x) {
    __shared__ __align__(16) __nv_bfloat16 Ts[64 * TSTR];

    const int tid  = threadIdx.x;
    const int w    = tid >> 5;
    const int lane = tid & 31;
    const int gid  = lane >> 2;
    const int tig  = lane & 3;
    const int b    = blockIdx.y;
    const long n0  = (long)blockIdx.x * GCHUNK;

    const int lr = tid >> 1, lh = tid & 1;
    const float* src = x + (long)b * CN + (long)lr * NCOL + n0 + lh * 16;

    const uint32_t ts0 = smem_u32(Ts);
    // A ldsm addr (per kk add 32B): row = w*16 + (l&7) + ((l>>3)&1)*8, col = (l>>4)*8
    const uint32_t aAddr = ts0 +
        (uint32_t)((w * 16 + (lane & 7) + ((lane >> 3) & 1) * 8) * TSTR +
                   ((lane >> 4) * 8)) * 2;
    // B ldsm addr (p = nt pair; per kk add 32B): row = 16p + ((l>>4)&1)*8 + (l&7),
    // col = ((l>>3)&1)*8
    const uint32_t bAddr0 = ts0 +
        (uint32_t)((((lane >> 4) & 1) * 8 + (lane & 7)) * TSTR +
                   (((lane >> 3) & 1) * 8)) * 2;

    float4 pf[4];
#pragma unroll
    for (int j = 0; j < 4; j++) pf[j] = *(const float4*)(src + j * 4);

    float acc[8][4] = {};

    for (int it = 0; it < GITERS; it++) {
        __syncthreads();
        {
            uint4 s0 = make_uint4(pk2(pf[0].x, pf[0].y), pk2(pf[0].z, pf[0].w),
                                  pk2(pf[1].x, pf[1].y), pk2(pf[1].z, pf[1].w));
            uint4 s1 = make_uint4(pk2(pf[2].x, pf[2].y), pk2(pf[2].z, pf[2].w),
                                  pk2(pf[3].x, pf[3].y), pk2(pf[3].z, pf[3].w));
            __nv_bfloat16* d = &Ts[lr * TSTR + lh * 16];
            *(uint4*)(d)     = s0;
            *(uint4*)(d + 8) = s1;
        }
        if (it + 1 < GITERS) {
            const float* s = src + (it + 1) * GKS;
#pragma unroll
            for (int j = 0; j < 4; j++) pf[j] = *(const float4*)(s + j * 4);
        }
        __syncthreads();

#pragma unroll
        for (int kk = 0; kk < 2; kk++) {
            uint32_t a[4];
            ldsm4(a, aAddr + kk * 32);
            uint32_t br[16];
#pragma unroll
            for (int p = 0; p < 4; p++)
                ldsm4(br + p * 4, bAddr0 + (uint32_t)(p * 16 * TSTR * 2) + kk * 32);
#pragma unroll
            for (int p = 0; p < 4; p++) {
                mma16816(acc[2 * p],     a, br + p * 4);
                mma16816(acc[2 * p + 1], a, br + p * 4 + 2);
            }
        }
    }

    float* op = g_part + ((long)b * NCHUNK + blockIdx.x) * (CCH * CCH);
#pragma unroll
    for (int nt = 0; nt < 8; nt++) {
        const int c0  = w * 16 + gid;
        const int col = nt * 8 + tig * 2;
        *(float2*)&op[c0 * CCH + col]       = make_float2(acc[nt][0], acc[nt][1]);
        *(float2*)&op[(c0 + 8) * CCH + col] = make_float2(acc[nt][2], acc[nt][3]);
    }
}

// ---------------------------------------------------------------------------
// Kernel 2a: reduce partials -> G.  grid (16, BATCH), 256 threads.
// ---------------------------------------------------------------------------
__global__ void reduce_g() {
    const int b    = blockIdx.y;
    const int elem = blockIdx.x * 256 + threadIdx.x;
    const float* p = g_part + (long)b * NCHUNK * (CCH * CCH) + elem;

    float s0 = 0.f, s1 = 0.f, s2 = 0.f, s3 = 0.f;
#pragma unroll 1
    for (int ch = 0; ch < NCHUNK; ch += 4) {
        s0 += p[(long)(ch + 0) * (CCH * CCH)];
        s1 += p[(long)(ch + 1) * (CCH * CCH)];
        s2 += p[(long)(ch + 2) * (CCH * CCH)];
        s3 += p[(long)(ch + 3) * (CCH * CCH)];
    }
    g_G[b * (CCH * CCH) + elem] = (s0 + s1) + (s2 + s3);
}

// ---------------------------------------------------------------------------
// Kernel 2b: m3 = G@G (symmetric), sigmoid -> bf16.  grid (BATCH).
// ---------------------------------------------------------------------------
__global__ void m3_sigmoid() {
    __shared__ float Gs[CCH * CCH];
    const int b   = blockIdx.x;
    const int tid = threadIdx.x;              // 256

    const float4* src = (const float4*)(g_G + b * (CCH * CCH));
    for (int i = tid; i < (CCH * CCH) / 4; i += 256)
        ((float4*)Gs)[i] = src[i];
    __syncthreads();

    const int c  = tid >> 2;
    const int e0 = (tid & 3) * 16;
    for (int e = e0; e < e0 + 16; e++) {
        float s = 0.0f;
#pragma unroll
        for (int d = 0; d < CCH; d++)
            s = fmaf(Gs[c * CCH + d], Gs[e * CCH + d], s);
        g_aff_bf[b * (CCH * CCH) + c * CCH + e] =
            __float2bfloat16(1.0f / (1.0f + __expf(-s)));
    }
}

// ---------------------------------------------------------------------------
// Kernel 3: out = x + gamma * (A @ K) via HMMA + ldmatrix.  M=64, N=96, K=64.
// x tile stored twice at load: fp32 Xs (residual) and bf16 Ks[d][n] (B-op via
// ldmatrix.trans — no explicit transpose phase).  256 threads / 8 warps:
// wm = w>>2 -> m-rows wm*32..+31; wn = w&3 -> n-cols wn*24..+23.
// ---------------------------------------------------------------------------
#define XSTR 100
#define ASTR 72
#define KSTR 104

__global__ void __launch_bounds__(256) weights_tc(const float* __restrict__ x,
                                                  const float* __restrict__ gamma_p,
                                                  float* __restrict__ out) {
    __shared__ __align__(16) float         Xs[64 * XSTR];   // 25600 B
    __shared__ __align__(16) __nv_bfloat16 As[64 * ASTR];   //  9216 B
    __shared__ __align__(16) __nv_bfloat16 Ks[64 * KSTR];   // 13312 B (48128 total)

    const int tid  = threadIdx.x;
    const int w    = tid >> 5;
    const int lane = tid & 31;
    const int gid  = lane >> 2;
    const int tig  = lane & 3;
    const int wm   = w >> 2;
    const int wn   = w & 3;
    const int b    = blockIdx.y;
    const long n0  = (long)blockIdx.x * WTN;

    const float g = *gamma_p;

    // load x tile fp32: 4 threads/row, 24 floats each -> Xs fp32 + Ks bf16
    {
        const int r = tid >> 2, q = tid & 3;
        const float* s = x + (long)b * CN + (long)r * NCOL + n0 + q * 24;
        float4 v[6];
#pragma unroll
        for (int i = 0; i < 6; i++) v[i] = *(const float4*)(s + i * 4);
        float* dx = &Xs[r * XSTR + q * 24];
#pragma unroll
        for (int i = 0; i < 6; i++) *(float4*)(dx + i * 4) = v[i];
        __nv_bfloat16* dk = &Ks[r * KSTR + q * 24];
#pragma unroll
        for (int i = 0; i < 3; i++) {
            *(uint4*)(dk + i * 8) = make_uint4(
                pk2(v[2 * i].x, v[2 * i].y),   pk2(v[2 * i].z, v[2 * i].w),
                pk2(v[2 * i + 1].x, v[2 * i + 1].y), pk2(v[2 * i + 1].z, v[2 * i + 1].w));
        }
    }
    // load affinity bf16 -> As[64][64] (stride 72)
    {
        const int r = tid >> 2, h = tid & 3;
        const uint4* s = (const uint4*)(g_aff_bf + b * (CCH * CCH) + r * CCH + h * 16);
        *(uint4*)&As[r * ASTR + h * 16]     = s[0];
        *(uint4*)&As[r * ASTR + h * 16 + 8] = s[1];
    }
    __syncthreads();

    const uint32_t as0 = smem_u32(As);
    const uint32_t ks0 = smem_u32(Ks);
    // A ldsm (non-trans) addr for mi: row = (wm*2+mi)*16 + (l&7) + ((l>>3)&1)*8,
    // col = (l>>4)*8 ; per kt add 32B.
    uint32_t aAddr[2];
#pragma unroll
    for (int mi = 0; mi < 2; mi++)
        aAddr[mi] = as0 + (uint32_t)((((wm * 2 + mi) * 16 + (lane & 7) +
                    ((lane >> 3) & 1) * 8) * ASTR + (lane >> 4) * 8)) * 2;
    // B ldsm.trans x4 (nt 0,1): krow = ((l>>3)&1)*8 + (l&7),
    // ncol = wn*24 + ((l>>4)&1)*8 ; per kt add 16*KSTR*2.
    const uint32_t b4Addr = ks0 + (uint32_t)(((((lane >> 3) & 1) * 8 + (lane & 7)) * KSTR
                          + wn * 24 + ((lane >> 4) & 1) * 8)) * 2;
    // B ldsm.trans x2 (nt 2): lanes 0-15 supply addrs; ncol = wn*24 + 16.
    const uint32_t b2Addr = ks0 + (uint32_t)(((((lane >> 3) & 1) * 8 + (lane & 7)) * KSTR
                          + wn * 24 + 16)) * 2;

    float acc[2][3][4] = {};

#pragma unroll
    for (int kt = 0; kt < 4; kt++) {
        uint32_t a0[4], a1[4], b01[4], b2[2];
        ldsm4 (a0,  aAddr[0] + kt * 32);
        ldsm4 (a1,  aAddr[1] + kt * 32);
        ldsm4t(b01, b4Addr + kt * (16 * KSTR * 2));
        ldsm2t(b2,  b2Addr + kt * (16 * KSTR * 2));
        mma16816(acc[0][0], a0, b01);
        mma16816(acc[0][1], a0, b01 + 2);
        mma16816(acc[0][2], a0, b2);
        mma16816(acc[1][0], a1, b01);
        mma16816(acc[1][1], a1, b01 + 2);
        mma16816(acc[1][2], a1, b2);
    }

#pragma unroll
    for (int mi = 0; mi < 2; mi++) {
#pragma unroll
        for (int nt = 0; nt < 3; nt++) {
            const int c0 = (wm * 2 + mi) * 16 + gid;
            const int n  = wn * 24 + nt * 8 + tig * 2;
            float2 x0 = *(float2*)&Xs[c0 * XSTR + n];
            float2 x1 = *(float2*)&Xs[(c0 + 8) * XSTR + n];
            float* d0 = out + (long)b * CN + (long)c0 * NCOL + n0 + n;
            float* d1 = d0 + 8l * NCOL;
            *(float2*)d0 = make_float2(fmaf(g, acc[mi][nt][0], x0.x),
                                       fmaf(g, acc[mi][nt][1], x0.y));
            *(float2*)d1 = make_float2(fmaf(g, acc[mi][nt][2], x1.x),
                                       fmaf(g, acc[mi][nt][3], x1.y));
        }
    }
}

// ---------------------------------------------------------------------------
extern "C" void kernel_launch(void* const* d_in, const int* in_sizes, int n_in,
                              void* d_out, int out_size) {
    const float* x     = (const float*)d_in[0];
    const float* gamma = (const float*)d_in[1];
    float*       out   = (float*)d_out;

    gram_tc    <<<dim3(NCHUNK, BATCH), 128>>>(x);
    reduce_g   <<<dim3(16, BATCH), 256>>>();
    m3_sigmoid <<<BATCH, 256>>>();
    weights_tc <<<dim3(WBLK, BATCH), 256>>>(x, gamma, out);
}